// round 1
// baseline (speedup 1.0000x reference)
#include <cuda_runtime.h>
#include <math.h>

#define TPB 256
#define NBATCH 16
#define NBOX 64
#define NCLS 30

// softplus blocks: scale0 -> 400 blocks (102400 cells), scale1 -> 100, scale2 -> 25
#define SP_BLOCKS 525
#define AS_BLOCKS 48           // 3 scales * 16 batches
#define TOTAL_BLOCKS (SP_BLOCKS + AS_BLOCKS)

// partial sums (written with .cg stores, read with .cg loads by last block)
__device__ float g_blk_sp[SP_BLOCKS];
__device__ float g_blk_as[AS_BLOCKS][4];   // cls_sum, reg_sum, obj_pos_sum, npos
__device__ unsigned int g_done = 0;

static __device__ __forceinline__ float softplus_f(float x) {
    // matches jax.nn.softplus = logaddexp(x, 0)
    return log1pf(expf(-fabsf(x))) + fmaxf(x, 0.0f);
}

// block reduce over 256 threads; result valid on thread 0
static __device__ __forceinline__ float blk_reduce(float v) {
    __shared__ float sh[TPB / 32];
    __syncthreads();  // protect shared reuse across sequential calls
    #pragma unroll
    for (int o = 16; o > 0; o >>= 1) v += __shfl_down_sync(0xffffffffu, v, o);
    int lane = threadIdx.x & 31, w = threadIdx.x >> 5;
    if (lane == 0) sh[w] = v;
    __syncthreads();
    v = (threadIdx.x < TPB / 32) ? sh[threadIdx.x] : 0.0f;
    if (w == 0) {
        #pragma unroll
        for (int o = TPB / 64; o > 0; o >>= 1) v += __shfl_down_sync(0xffffffffu, v, o);
    }
    return v;
}

__global__ __launch_bounds__(TPB)
void detloss_kernel(const float* __restrict__ cls0, const float* __restrict__ cls1,
                    const float* __restrict__ cls2,
                    const float* __restrict__ reg0, const float* __restrict__ reg1,
                    const float* __restrict__ reg2,
                    const float* __restrict__ obj0, const float* __restrict__ obj1,
                    const float* __restrict__ obj2,
                    const float* __restrict__ boxes, const int* __restrict__ labels,
                    float* __restrict__ out)
{
    const float* clsp[3] = {cls0, cls1, cls2};
    const float* regp[3] = {reg0, reg1, reg2};
    const float* objp[3] = {obj0, obj1, obj2};

    int bid = blockIdx.x;
    int t = threadIdx.x;

    if (bid < SP_BLOCKS) {
        // ---- objectness softplus sum over all cells ----
        int s, lo;
        if (bid < 400)      { s = 0; lo = bid * TPB; }
        else if (bid < 500) { s = 1; lo = (bid - 400) * TPB; }
        else                { s = 2; lo = (bid - 500) * TPB; }
        float x = objp[s][lo + t];
        float tot = blk_reduce(softplus_f(x));
        if (t == 0) __stcg(&g_blk_sp[bid], tot);
    } else {
        // ---- per (scale, batch) assignment + positive-cell losses ----
        int idx = bid - SP_BLOCKS;
        int s = idx >> 4;         // 0..2
        int b = idx & 15;         // 0..15
        int Wd = 80 >> s;         // 80, 40, 20
        int HW = Wd * Wd;

        __shared__ int scell[NBOX];
        __shared__ int slab[NBOX];

        if (t < NBOX) {
            const float* bx = boxes + (size_t)(b * NBOX + t) * 4;
            float cx = bx[0], cy = bx[1];
            int gx = (int)(cx * (float)Wd);
            int gy = (int)(cy * (float)Wd);
            gx = max(0, min(gx, Wd - 1));
            gy = max(0, min(gy, Wd - 1));
            scell[t] = gy * Wd + gx;
            slab[t]  = labels[b * NBOX + t];
        }
        __syncthreads();

        float cls_l = 0.0f, reg_l = 0.0f, objp_l = 0.0f, np_l = 0.0f;
        if (t < NBOX) {
            int cell = scell[t];
            bool winner = true;         // last-writer-wins: max n within this cell
            int ml = slab[t];           // argmax(one-hot) tie-break: min label in cell
            #pragma unroll 1
            for (int j = 0; j < NBOX; j++) {
                if (j == t) continue;
                if (scell[j] == cell) {
                    if (j > t) winner = false;
                    ml = min(ml, slab[j]);
                }
            }
            if (winner) {
                np_l = 1.0f;
                objp_l = objp[s][(size_t)b * HW + cell];

                // classification: online logsumexp over 30 classes (strided HW)
                const float* cp = clsp[s] + (size_t)b * NCLS * HW + cell;
                float m = -INFINITY, ssum = 0.0f, tgt = 0.0f;
                #pragma unroll 1
                for (int c = 0; c < NCLS; c++) {
                    float v = cp[(size_t)c * HW];
                    if (c == ml) tgt = v;
                    float nm = fmaxf(m, v);
                    ssum = ssum * expf(m - nm) + expf(v - nm);
                    m = nm;
                }
                cls_l = m + logf(ssum) - tgt;

                // regression: smooth-L1 (beta=1) vs this box (winner == last writer)
                const float* rp  = regp[s] + (size_t)b * 4 * HW + cell;
                const float* bxx = boxes + (size_t)(b * NBOX + t) * 4;
                float sl = 0.0f;
                #pragma unroll
                for (int c = 0; c < 4; c++) {
                    float d = fabsf(rp[(size_t)c * HW] - bxx[c]);
                    sl += (d < 1.0f) ? 0.5f * d * d : d - 0.5f;
                }
                sl *= 0.25f;
                reg_l = fminf(sl, 10.0f);
            }
        }
        float r;
        r = blk_reduce(cls_l);  if (t == 0) __stcg(&g_blk_as[idx][0], r);
        r = blk_reduce(reg_l);  if (t == 0) __stcg(&g_blk_as[idx][1], r);
        r = blk_reduce(objp_l); if (t == 0) __stcg(&g_blk_as[idx][2], r);
        r = blk_reduce(np_l);   if (t == 0) __stcg(&g_blk_as[idx][3], r);
    }

    // ---- last block does the deterministic final reduce ----
    __shared__ bool amLast;
    __threadfence();
    if (t == 0) {
        unsigned v = atomicAdd(&g_done, 1u);
        amLast = (v == (unsigned)(gridDim.x - 1));
    }
    __syncthreads();
    if (!amLast) return;

    float sp[3];
    #pragma unroll
    for (int s = 0; s < 3; s++) {
        int lo = (s == 0) ? 0 : (s == 1) ? 400 : 500;
        int hi = (s == 0) ? 400 : (s == 1) ? 500 : 525;
        float loc = 0.0f;
        for (int i = lo + t; i < hi; i += TPB) loc += __ldcg(&g_blk_sp[i]);
        sp[s] = blk_reduce(loc);   // valid on thread 0
    }

    if (t == 0) {
        float cls_tot = 0.0f, reg_tot = 0.0f, obj_tot = 0.0f;
        #pragma unroll
        for (int s = 0; s < 3; s++) {
            float c = 0.0f, rg = 0.0f, op = 0.0f, np = 0.0f;
            #pragma unroll
            for (int i = 0; i < NBATCH; i++) {
                c  += __ldcg(&g_blk_as[s * NBATCH + i][0]);
                rg += __ldcg(&g_blk_as[s * NBATCH + i][1]);
                op += __ldcg(&g_blk_as[s * NBATCH + i][2]);
                np += __ldcg(&g_blk_as[s * NBATCH + i][3]);
            }
            float npos = fmaxf(np, 1.0f);
            int Wd = 80 >> s;
            float Ms = (float)(NBATCH * Wd * Wd);
            cls_tot += c / npos;               // CLS_W = 1
            reg_tot += rg / npos * 5.0f;       // REG_W = 5
            obj_tot += (sp[s] - op) / Ms;      // OBJ_W = 1
        }
        cls_tot *= (1.0f / 3.0f);
        reg_tot *= (1.0f / 3.0f);
        obj_tot *= (1.0f / 3.0f);
        out[0] = cls_tot + reg_tot + obj_tot;
        out[1] = cls_tot;
        out[2] = reg_tot;
        out[3] = obj_tot;
        g_done = 0;   // reset for next graph replay
    }
}

extern "C" void kernel_launch(void* const* d_in, const int* in_sizes, int n_in,
                              void* d_out, int out_size)
{
    const float *cls[3], *reg[3], *obj[3];
    // Disambiguate metadata ordering by sizes:
    //   dict order:      cls0(3072000), reg0(409600), obj0(102400), cls1, reg1, obj1, cls2, reg2, obj2
    //   signature order: cls0, cls1(768000), cls2, reg0, reg1, reg2, obj0, obj1, obj2
    if (in_sizes[1] == 409600) {
        cls[0] = (const float*)d_in[0]; reg[0] = (const float*)d_in[1]; obj[0] = (const float*)d_in[2];
        cls[1] = (const float*)d_in[3]; reg[1] = (const float*)d_in[4]; obj[1] = (const float*)d_in[5];
        cls[2] = (const float*)d_in[6]; reg[2] = (const float*)d_in[7]; obj[2] = (const float*)d_in[8];
    } else {
        cls[0] = (const float*)d_in[0]; cls[1] = (const float*)d_in[1]; cls[2] = (const float*)d_in[2];
        reg[0] = (const float*)d_in[3]; reg[1] = (const float*)d_in[4]; reg[2] = (const float*)d_in[5];
        obj[0] = (const float*)d_in[6]; obj[1] = (const float*)d_in[7]; obj[2] = (const float*)d_in[8];
    }
    const float* boxes  = (const float*)d_in[9];
    const int*   labels = (const int*)d_in[10];
    float* out = (float*)d_out;

    detloss_kernel<<<TOTAL_BLOCKS, TPB>>>(
        cls[0], cls[1], cls[2],
        reg[0], reg[1], reg[2],
        obj[0], obj[1], obj[2],
        boxes, labels, out);
}

// round 2
// speedup vs baseline: 1.4636x; 1.4636x over previous
#include <cuda_runtime.h>
#include <math.h>

#define TPB 256
#define NBATCH 16
#define NBOX 64
#define NCLS 30

// softplus blocks (float4 per thread):
//   scale0: 102400 floats = 25600 f4 -> 100 blocks
//   scale1:  25600 floats =  6400 f4 ->  25 blocks
//   scale2:   6400 floats =  1600 f4 ->   7 blocks (guarded)
#define SP0_BLOCKS 100
#define SP1_BLOCKS 25
#define SP2_BLOCKS 7
#define SP_BLOCKS (SP0_BLOCKS + SP1_BLOCKS + SP2_BLOCKS)   // 132
#define AS_BLOCKS 48                                        // 3 scales * 16 batches
#define TOTAL_BLOCKS (SP_BLOCKS + AS_BLOCKS)                // 180

__device__ float g_blk_sp[SP_BLOCKS];
__device__ float g_blk_as[AS_BLOCKS][4];   // cls_sum, reg_sum, obj_pos_sum, npos
__device__ unsigned int g_done = 0;

static __device__ __forceinline__ float softplus_f(float x) {
    return fmaxf(x, 0.0f) + __logf(1.0f + __expf(-fabsf(x)));
}

// block reduce over TPB threads; result valid on thread 0
static __device__ __forceinline__ float blk_reduce(float v) {
    __shared__ float sh[TPB / 32];
    __syncthreads();
    #pragma unroll
    for (int o = 16; o > 0; o >>= 1) v += __shfl_down_sync(0xffffffffu, v, o);
    int lane = threadIdx.x & 31, w = threadIdx.x >> 5;
    if (lane == 0) sh[w] = v;
    __syncthreads();
    v = (threadIdx.x < TPB / 32) ? sh[threadIdx.x] : 0.0f;
    if (w == 0) {
        #pragma unroll
        for (int o = TPB / 64; o > 0; o >>= 1) v += __shfl_down_sync(0xffffffffu, v, o);
    }
    return v;
}

// fused 4-value block reduce (2 barriers total); results valid on thread 0
static __device__ __forceinline__ void blk_reduce4(float v0, float v1, float v2, float v3,
                                                   float* r) {
    __shared__ float sh[TPB / 32][4];
    __syncthreads();
    #pragma unroll
    for (int o = 16; o > 0; o >>= 1) {
        v0 += __shfl_down_sync(0xffffffffu, v0, o);
        v1 += __shfl_down_sync(0xffffffffu, v1, o);
        v2 += __shfl_down_sync(0xffffffffu, v2, o);
        v3 += __shfl_down_sync(0xffffffffu, v3, o);
    }
    int lane = threadIdx.x & 31, w = threadIdx.x >> 5;
    if (lane == 0) { sh[w][0] = v0; sh[w][1] = v1; sh[w][2] = v2; sh[w][3] = v3; }
    __syncthreads();
    if (threadIdx.x == 0) {
        float a = 0.f, b = 0.f, c = 0.f, d = 0.f;
        #pragma unroll
        for (int i = 0; i < TPB / 32; i++) {
            a += sh[i][0]; b += sh[i][1]; c += sh[i][2]; d += sh[i][3];
        }
        r[0] = a; r[1] = b; r[2] = c; r[3] = d;
    }
}

__global__ __launch_bounds__(TPB)
void detloss_kernel(const float* __restrict__ cls0, const float* __restrict__ cls1,
                    const float* __restrict__ cls2,
                    const float* __restrict__ reg0, const float* __restrict__ reg1,
                    const float* __restrict__ reg2,
                    const float* __restrict__ obj0, const float* __restrict__ obj1,
                    const float* __restrict__ obj2,
                    const float* __restrict__ boxes, const int* __restrict__ labels,
                    float* __restrict__ out)
{
    const float* clsp[3] = {cls0, cls1, cls2};
    const float* regp[3] = {reg0, reg1, reg2};
    const float* objp[3] = {obj0, obj1, obj2};

    int bid = blockIdx.x;
    int t = threadIdx.x;

    if (bid < SP_BLOCKS) {
        // ---- objectness softplus sum, float4 per thread ----
        const float4* src;
        int idx, lim;
        if (bid < SP0_BLOCKS) {
            src = (const float4*)obj0; idx = bid * TPB + t; lim = 25600;
        } else if (bid < SP0_BLOCKS + SP1_BLOCKS) {
            src = (const float4*)obj1; idx = (bid - SP0_BLOCKS) * TPB + t; lim = 6400;
        } else {
            src = (const float4*)obj2; idx = (bid - SP0_BLOCKS - SP1_BLOCKS) * TPB + t; lim = 1600;
        }
        float acc = 0.0f;
        if (idx < lim) {
            float4 v = src[idx];
            acc = softplus_f(v.x) + softplus_f(v.y) + softplus_f(v.z) + softplus_f(v.w);
        }
        float tot = blk_reduce(acc);
        if (t == 0) __stcg(&g_blk_sp[bid], tot);
    } else {
        // ---- per (scale, batch): assignment + positive-cell losses ----
        int idx = bid - SP_BLOCKS;
        int s = idx >> 4;          // 0..2
        int b = idx & 15;          // 0..15
        int Wd = 80 >> s;          // 80, 40, 20
        int HW = Wd * Wd;

        __shared__ int scell[NBOX];
        __shared__ int slab[NBOX];

        if (t < NBOX) {
            const float* bx = boxes + (size_t)(b * NBOX + t) * 4;
            float cx = bx[0], cy = bx[1];
            int gx = (int)(cx * (float)Wd);
            int gy = (int)(cy * (float)Wd);
            gx = max(0, min(gx, Wd - 1));
            gy = max(0, min(gy, Wd - 1));
            scell[t] = gy * Wd + gx;
            slab[t]  = labels[b * NBOX + t];
        }
        __syncthreads();

        float cls_l = 0.0f, reg_l = 0.0f, objp_l = 0.0f, np_l = 0.0f;
        if (t < NBOX) {
            int cell = scell[t];
            bool winner = true;          // last-writer-wins: highest box index in cell
            int ml = slab[t];            // argmax(one-hot) tie-break: min label in cell
            #pragma unroll 1
            for (int j = 0; j < NBOX; j++) {
                if (j == t) continue;
                if (scell[j] == cell) {
                    if (j > t) winner = false;
                    ml = min(ml, slab[j]);
                }
            }
            if (winner) {
                np_l = 1.0f;
                objp_l = __ldg(&objp[s][(size_t)b * HW + cell]);

                // classification: fully-unrolled loads -> all 30 in flight at once
                const float* cp = clsp[s] + (size_t)b * NCLS * HW + cell;
                float v[NCLS];
                #pragma unroll
                for (int c = 0; c < NCLS; c++) v[c] = __ldg(&cp[(size_t)c * HW]);

                float m = v[0];
                #pragma unroll
                for (int c = 1; c < NCLS; c++) m = fmaxf(m, v[c]);
                float ssum = 0.0f, tgt = 0.0f;
                #pragma unroll
                for (int c = 0; c < NCLS; c++) {
                    ssum += __expf(v[c] - m);
                    if (c == ml) tgt = v[c];
                }
                cls_l = m + __logf(ssum) - tgt;

                // regression: smooth-L1 (beta=1) vs winning (= this) box
                const float* rp  = regp[s] + (size_t)b * 4 * HW + cell;
                const float* bxx = boxes + (size_t)(b * NBOX + t) * 4;
                float r0 = __ldg(&rp[0]);
                float r1 = __ldg(&rp[(size_t)HW]);
                float r2 = __ldg(&rp[(size_t)2 * HW]);
                float r3 = __ldg(&rp[(size_t)3 * HW]);
                float sl = 0.0f;
                float d;
                d = fabsf(r0 - bxx[0]); sl += (d < 1.0f) ? 0.5f * d * d : d - 0.5f;
                d = fabsf(r1 - bxx[1]); sl += (d < 1.0f) ? 0.5f * d * d : d - 0.5f;
                d = fabsf(r2 - bxx[2]); sl += (d < 1.0f) ? 0.5f * d * d : d - 0.5f;
                d = fabsf(r3 - bxx[3]); sl += (d < 1.0f) ? 0.5f * d * d : d - 0.5f;
                sl *= 0.25f;
                reg_l = fminf(sl, 10.0f);
            }
        }
        __shared__ float res[4];
        blk_reduce4(cls_l, reg_l, objp_l, np_l, res);
        if (t == 0) {
            __stcg(&g_blk_as[idx][0], res[0]);
            __stcg(&g_blk_as[idx][1], res[1]);
            __stcg(&g_blk_as[idx][2], res[2]);
            __stcg(&g_blk_as[idx][3], res[3]);
        }
    }

    // ---- last arriving block: deterministic final reduce ----
    __shared__ bool amLast;
    __threadfence();
    if (t == 0) {
        unsigned v = atomicAdd(&g_done, 1u);
        amLast = (v == (unsigned)(gridDim.x - 1));
    }
    __syncthreads();
    if (!amLast) return;

    float sp[3];
    #pragma unroll
    for (int s = 0; s < 3; s++) {
        int lo = (s == 0) ? 0 : (s == 1) ? SP0_BLOCKS : SP0_BLOCKS + SP1_BLOCKS;
        int hi = (s == 0) ? SP0_BLOCKS : (s == 1) ? SP0_BLOCKS + SP1_BLOCKS : SP_BLOCKS;
        float loc = 0.0f;
        for (int i = lo + t; i < hi; i += TPB) loc += __ldcg(&g_blk_sp[i]);
        sp[s] = blk_reduce(loc);   // valid on thread 0
    }

    if (t == 0) {
        float cls_tot = 0.0f, reg_tot = 0.0f, obj_tot = 0.0f;
        #pragma unroll
        for (int s = 0; s < 3; s++) {
            float c = 0.0f, rg = 0.0f, op = 0.0f, np = 0.0f;
            #pragma unroll
            for (int i = 0; i < NBATCH; i++) {
                c  += __ldcg(&g_blk_as[s * NBATCH + i][0]);
                rg += __ldcg(&g_blk_as[s * NBATCH + i][1]);
                op += __ldcg(&g_blk_as[s * NBATCH + i][2]);
                np += __ldcg(&g_blk_as[s * NBATCH + i][3]);
            }
            float npos = fmaxf(np, 1.0f);
            int Wd = 80 >> s;
            float Ms = (float)(NBATCH * Wd * Wd);
            cls_tot += c / npos;               // CLS_W = 1
            reg_tot += rg / npos * 5.0f;       // REG_W = 5
            obj_tot += (sp[s] - op) / Ms;      // OBJ_W = 1
        }
        cls_tot *= (1.0f / 3.0f);
        reg_tot *= (1.0f / 3.0f);
        obj_tot *= (1.0f / 3.0f);
        out[0] = cls_tot + reg_tot + obj_tot;
        out[1] = cls_tot;
        out[2] = reg_tot;
        out[3] = obj_tot;
        g_done = 0;   // reset for next graph replay
    }
}

extern "C" void kernel_launch(void* const* d_in, const int* in_sizes, int n_in,
                              void* d_out, int out_size)
{
    const float *cls[3], *reg[3], *obj[3];
    if (in_sizes[1] == 409600) {   // dict order: cls0,reg0,obj0,cls1,...
        cls[0] = (const float*)d_in[0]; reg[0] = (const float*)d_in[1]; obj[0] = (const float*)d_in[2];
        cls[1] = (const float*)d_in[3]; reg[1] = (const float*)d_in[4]; obj[1] = (const float*)d_in[5];
        cls[2] = (const float*)d_in[6]; reg[2] = (const float*)d_in[7]; obj[2] = (const float*)d_in[8];
    } else {                        // signature order: cls0,cls1,cls2,reg0,...
        cls[0] = (const float*)d_in[0]; cls[1] = (const float*)d_in[1]; cls[2] = (const float*)d_in[2];
        reg[0] = (const float*)d_in[3]; reg[1] = (const float*)d_in[4]; reg[2] = (const float*)d_in[5];
        obj[0] = (const float*)d_in[6]; obj[1] = (const float*)d_in[7]; obj[2] = (const float*)d_in[8];
    }
    const float* boxes  = (const float*)d_in[9];
    const int*   labels = (const int*)d_in[10];
    float* out = (float*)d_out;

    detloss_kernel<<<TOTAL_BLOCKS, TPB>>>(
        cls[0], cls[1], cls[2],
        reg[0], reg[1], reg[2],
        obj[0], obj[1], obj[2],
        boxes, labels, out);
}

// round 3
// speedup vs baseline: 1.6589x; 1.1335x over previous
#include <cuda_runtime.h>
#include <math.h>

#define TPB 256
#define NBATCH 16
#define NBOX 64
#define NCLS 30

// softplus blocks: each handles 512 float4 (2048 floats): 2 f4 per thread
//   scale0: 25600 f4 -> 50 blocks ; scale1: 6400 f4 -> 13 blocks (guarded)
//   scale2: 1600 f4 -> 4 blocks (guarded)
#define SP0_BLOCKS 50
#define SP1_BLOCKS 13
#define SP2_BLOCKS 4
#define SP_BLOCKS (SP0_BLOCKS + SP1_BLOCKS + SP2_BLOCKS)   // 67
#define AS_BLOCKS 48                                        // 3 scales * 16 batches
#define TOTAL_BLOCKS (SP_BLOCKS + AS_BLOCKS)                // 115

__device__ float g_blk_sp[SP_BLOCKS];
__device__ float g_blk_as[AS_BLOCKS][4];   // cls_sum, reg_sum, obj_pos_sum, npos
__device__ unsigned int g_done = 0;

static __device__ __forceinline__ float softplus_f(float x) {
    return fmaxf(x, 0.0f) + __logf(1.0f + __expf(-fabsf(x)));
}

// block reduce; result valid on thread 0
static __device__ __forceinline__ float blk_reduce(float v) {
    __shared__ float sh[TPB / 32];
    __syncthreads();
    #pragma unroll
    for (int o = 16; o > 0; o >>= 1) v += __shfl_down_sync(0xffffffffu, v, o);
    int lane = threadIdx.x & 31, w = threadIdx.x >> 5;
    if (lane == 0) sh[w] = v;
    __syncthreads();
    v = (threadIdx.x < TPB / 32) ? sh[threadIdx.x] : 0.0f;
    if (w == 0) {
        #pragma unroll
        for (int o = TPB / 64; o > 0; o >>= 1) v += __shfl_down_sync(0xffffffffu, v, o);
    }
    return v;
}

// fused 4-value block reduce (2 barriers); results valid on thread 0 in r[0..3]
static __device__ __forceinline__ void blk_reduce4(float v0, float v1, float v2, float v3,
                                                   float* r) {
    __shared__ float sh[TPB / 32][4];
    __syncthreads();
    #pragma unroll
    for (int o = 16; o > 0; o >>= 1) {
        v0 += __shfl_down_sync(0xffffffffu, v0, o);
        v1 += __shfl_down_sync(0xffffffffu, v1, o);
        v2 += __shfl_down_sync(0xffffffffu, v2, o);
        v3 += __shfl_down_sync(0xffffffffu, v3, o);
    }
    int lane = threadIdx.x & 31, w = threadIdx.x >> 5;
    if (lane == 0) { sh[w][0] = v0; sh[w][1] = v1; sh[w][2] = v2; sh[w][3] = v3; }
    __syncthreads();
    if (threadIdx.x == 0) {
        float a = 0.f, b = 0.f, c = 0.f, d = 0.f;
        #pragma unroll
        for (int i = 0; i < TPB / 32; i++) {
            a += sh[i][0]; b += sh[i][1]; c += sh[i][2]; d += sh[i][3];
        }
        r[0] = a; r[1] = b; r[2] = c; r[3] = d;
    }
}

__global__ __launch_bounds__(TPB)
void detloss_kernel(const float* __restrict__ cls0, const float* __restrict__ cls1,
                    const float* __restrict__ cls2,
                    const float* __restrict__ reg0, const float* __restrict__ reg1,
                    const float* __restrict__ reg2,
                    const float* __restrict__ obj0, const float* __restrict__ obj1,
                    const float* __restrict__ obj2,
                    const float* __restrict__ boxes, const int* __restrict__ labels,
                    float* __restrict__ out)
{
    const float* clsp[3] = {cls0, cls1, cls2};
    const float* regp[3] = {reg0, reg1, reg2};
    const float* objp[3] = {obj0, obj1, obj2};

    int bid = blockIdx.x;
    int t = threadIdx.x;

    if (bid < SP_BLOCKS) {
        // ---- objectness softplus sum: 2 float4 per thread ----
        const float4* src;
        int base, lim;
        if (bid < SP0_BLOCKS) {
            src = (const float4*)obj0; base = bid * 512; lim = 25600;
        } else if (bid < SP0_BLOCKS + SP1_BLOCKS) {
            src = (const float4*)obj1; base = (bid - SP0_BLOCKS) * 512; lim = 6400;
        } else {
            src = (const float4*)obj2; base = (bid - SP0_BLOCKS - SP1_BLOCKS) * 512; lim = 1600;
        }
        int i0 = base + t, i1 = base + 256 + t;
        float acc = 0.0f;
        if (i0 < lim) {
            float4 v = src[i0];
            acc += softplus_f(v.x) + softplus_f(v.y) + softplus_f(v.z) + softplus_f(v.w);
        }
        if (i1 < lim) {
            float4 v = src[i1];
            acc += softplus_f(v.x) + softplus_f(v.y) + softplus_f(v.z) + softplus_f(v.w);
        }
        float tot = blk_reduce(acc);
        if (t == 0) __stcg(&g_blk_sp[bid], tot);
    } else {
        // ---- per (scale, batch): assignment + positive-cell losses ----
        int idx = bid - SP_BLOCKS;
        int s = idx >> 4;          // 0..2
        int b = idx & 15;          // 0..15
        int Wd = 80 >> s;          // 80, 40, 20
        int HW = Wd * Wd;

        __shared__ int scell[NBOX];
        __shared__ int slab[NBOX];

        int cell = 0, mylab = 0;
        float objv = 0.0f, v[NCLS], r4[4], bxc[4];

        if (t < NBOX) {
            const float4 bx = ((const float4*)boxes)[b * NBOX + t];
            bxc[0] = bx.x; bxc[1] = bx.y; bxc[2] = bx.z; bxc[3] = bx.w;
            int gx = (int)(bx.x * (float)Wd);
            int gy = (int)(bx.y * (float)Wd);
            gx = max(0, min(gx, Wd - 1));
            gy = max(0, min(gy, Wd - 1));
            cell = gy * Wd + gx;
            mylab = labels[b * NBOX + t];
            scell[t] = cell;
            slab[t]  = mylab;

            // ---- speculative gathers for own cell (overlap with collision loop) ----
            objv = __ldg(&objp[s][(size_t)b * HW + cell]);
            const float* cp = clsp[s] + (size_t)b * NCLS * HW + cell;
            #pragma unroll
            for (int c = 0; c < NCLS; c++) v[c] = __ldg(&cp[(size_t)c * HW]);
            const float* rp = regp[s] + (size_t)b * 4 * HW + cell;
            #pragma unroll
            for (int c = 0; c < 4; c++) r4[c] = __ldg(&rp[(size_t)c * HW]);
        }
        __syncthreads();

        float cls_l = 0.0f, reg_l = 0.0f, objp_l = 0.0f, np_l = 0.0f;
        if (t < NBOX) {
            bool winner = true;          // last-writer-wins: highest box index in cell
            int ml = mylab;              // argmax(one-hot) tie-break: min label in cell
            #pragma unroll 1
            for (int j = 0; j < NBOX; j++) {
                if (j == t) continue;
                if (scell[j] == cell) {
                    if (j > t) winner = false;
                    ml = min(ml, slab[j]);
                }
            }
            if (winner) {
                np_l = 1.0f;
                objp_l = objv;

                float m = v[0];
                #pragma unroll
                for (int c = 1; c < NCLS; c++) m = fmaxf(m, v[c]);
                float ssum = 0.0f, tgt = 0.0f;
                #pragma unroll
                for (int c = 0; c < NCLS; c++) {
                    ssum += __expf(v[c] - m);
                    if (c == ml) tgt = v[c];
                }
                cls_l = m + __logf(ssum) - tgt;

                float sl = 0.0f;
                #pragma unroll
                for (int c = 0; c < 4; c++) {
                    float d = fabsf(r4[c] - bxc[c]);
                    sl += (d < 1.0f) ? 0.5f * d * d : d - 0.5f;
                }
                sl *= 0.25f;
                reg_l = fminf(sl, 10.0f);
            }
        }
        __shared__ float res[4];
        blk_reduce4(cls_l, reg_l, objp_l, np_l, res);
        if (t == 0) {
            __stcg(&g_blk_as[idx][0], res[0]);
            __stcg(&g_blk_as[idx][1], res[1]);
            __stcg(&g_blk_as[idx][2], res[2]);
            __stcg(&g_blk_as[idx][3], res[3]);
        }
    }

    // ---- last arriving block: deterministic final reduce ----
    __shared__ bool amLast;
    if (t == 0) {
        __threadfence();   // order this block's partial store before the ticket
        unsigned vv = atomicAdd(&g_done, 1u);
        amLast = (vv == (unsigned)(gridDim.x - 1));
        if (amLast) __threadfence();   // acquire: see all other blocks' partials
    }
    __syncthreads();
    if (!amLast) return;

    // softplus partials: one load per thread, fused 3-way reduce
    float l0 = 0.f, l1 = 0.f, l2 = 0.f;
    if (t < SP_BLOCKS) {
        float pv = __ldcg(&g_blk_sp[t]);
        if (t < SP0_BLOCKS) l0 = pv;
        else if (t < SP0_BLOCKS + SP1_BLOCKS) l1 = pv;
        else l2 = pv;
    }
    __shared__ float spr[4];
    blk_reduce4(l0, l1, l2, 0.0f, spr);

    if (t == 0) {
        float cls_tot = 0.0f, reg_tot = 0.0f, obj_tot = 0.0f;
        #pragma unroll
        for (int s = 0; s < 3; s++) {
            float c = 0.0f, rg = 0.0f, op = 0.0f, np = 0.0f;
            #pragma unroll
            for (int i = 0; i < NBATCH; i++) {
                c  += __ldcg(&g_blk_as[s * NBATCH + i][0]);
                rg += __ldcg(&g_blk_as[s * NBATCH + i][1]);
                op += __ldcg(&g_blk_as[s * NBATCH + i][2]);
                np += __ldcg(&g_blk_as[s * NBATCH + i][3]);
            }
            float npos = fmaxf(np, 1.0f);
            int Wd = 80 >> s;
            float Ms = (float)(NBATCH * Wd * Wd);
            cls_tot += c / npos;               // CLS_W = 1
            reg_tot += rg / npos * 5.0f;       // REG_W = 5
            obj_tot += (spr[s] - op) / Ms;     // OBJ_W = 1
        }
        cls_tot *= (1.0f / 3.0f);
        reg_tot *= (1.0f / 3.0f);
        obj_tot *= (1.0f / 3.0f);
        out[0] = cls_tot + reg_tot + obj_tot;
        out[1] = cls_tot;
        out[2] = reg_tot;
        out[3] = obj_tot;
        g_done = 0;   // reset for next graph replay
    }
}

extern "C" void kernel_launch(void* const* d_in, const int* in_sizes, int n_in,
                              void* d_out, int out_size)
{
    const float *cls[3], *reg[3], *obj[3];
    if (in_sizes[1] == 409600) {   // dict order: cls0,reg0,obj0,cls1,...
        cls[0] = (const float*)d_in[0]; reg[0] = (const float*)d_in[1]; obj[0] = (const float*)d_in[2];
        cls[1] = (const float*)d_in[3]; reg[1] = (const float*)d_in[4]; obj[1] = (const float*)d_in[5];
        cls[2] = (const float*)d_in[6]; reg[2] = (const float*)d_in[7]; obj[2] = (const float*)d_in[8];
    } else {                        // signature order: cls0,cls1,cls2,reg0,...
        cls[0] = (const float*)d_in[0]; cls[1] = (const float*)d_in[1]; cls[2] = (const float*)d_in[2];
        reg[0] = (const float*)d_in[3]; reg[1] = (const float*)d_in[4]; reg[2] = (const float*)d_in[5];
        obj[0] = (const float*)d_in[6]; obj[1] = (const float*)d_in[7]; obj[2] = (const float*)d_in[8];
    }
    const float* boxes  = (const float*)d_in[9];
    const int*   labels = (const int*)d_in[10];
    float* out = (float*)d_out;

    detloss_kernel<<<TOTAL_BLOCKS, TPB>>>(
        cls[0], cls[1], cls[2],
        reg[0], reg[1], reg[2],
        obj[0], obj[1], obj[2],
        boxes, labels, out);
}

// round 4
// speedup vs baseline: 2.4241x; 1.4613x over previous
#include <cuda_runtime.h>
#include <math.h>

#define TPB 256
#define NBATCH 16
#define NBOX 64
#define NCLS 30

// softplus blocks: each handles 512 float4 (2048 floats)
#define SP0_BLOCKS 50
#define SP1_BLOCKS 13
#define SP2_BLOCKS 4
#define SP_BLOCKS (SP0_BLOCKS + SP1_BLOCKS + SP2_BLOCKS)   // 67
#define AS_BLOCKS 48                                        // 3 scales * 16 batches
#define TOTAL_BLOCKS (SP_BLOCKS + AS_BLOCKS)                // 115

__device__ float  g_blk_sp[SP_BLOCKS];
__device__ float4 g_blk_as[AS_BLOCKS];     // {cls_sum, reg_sum, obj_pos_sum, npos}
__device__ unsigned int g_done = 0;

static __device__ __forceinline__ float softplus_f(float x) {
    return fmaxf(x, 0.0f) + __logf(1.0f + __expf(-fabsf(x)));
}

// block reduce; result valid on thread 0
static __device__ __forceinline__ float blk_reduce(float v) {
    __shared__ float sh[TPB / 32];
    __syncthreads();
    #pragma unroll
    for (int o = 16; o > 0; o >>= 1) v += __shfl_down_sync(0xffffffffu, v, o);
    int lane = threadIdx.x & 31, w = threadIdx.x >> 5;
    if (lane == 0) sh[w] = v;
    __syncthreads();
    v = (threadIdx.x < TPB / 32) ? sh[threadIdx.x] : 0.0f;
    if (w == 0) {
        #pragma unroll
        for (int o = TPB / 64; o > 0; o >>= 1) v += __shfl_down_sync(0xffffffffu, v, o);
    }
    return v;
}

// fused 4-value block reduce (2 barriers); results valid on thread 0 in r[0..3]
static __device__ __forceinline__ void blk_reduce4(float v0, float v1, float v2, float v3,
                                                   float* r) {
    __shared__ float sh[TPB / 32][4];
    __syncthreads();
    #pragma unroll
    for (int o = 16; o > 0; o >>= 1) {
        v0 += __shfl_down_sync(0xffffffffu, v0, o);
        v1 += __shfl_down_sync(0xffffffffu, v1, o);
        v2 += __shfl_down_sync(0xffffffffu, v2, o);
        v3 += __shfl_down_sync(0xffffffffu, v3, o);
    }
    int lane = threadIdx.x & 31, w = threadIdx.x >> 5;
    if (lane == 0) { sh[w][0] = v0; sh[w][1] = v1; sh[w][2] = v2; sh[w][3] = v3; }
    __syncthreads();
    if (threadIdx.x == 0) {
        float a = 0.f, b = 0.f, c = 0.f, d = 0.f;
        #pragma unroll
        for (int i = 0; i < TPB / 32; i++) {
            a += sh[i][0]; b += sh[i][1]; c += sh[i][2]; d += sh[i][3];
        }
        r[0] = a; r[1] = b; r[2] = c; r[3] = d;
    }
}

__global__ __launch_bounds__(TPB)
void detloss_kernel(const float* __restrict__ cls0, const float* __restrict__ cls1,
                    const float* __restrict__ cls2,
                    const float* __restrict__ reg0, const float* __restrict__ reg1,
                    const float* __restrict__ reg2,
                    const float* __restrict__ obj0, const float* __restrict__ obj1,
                    const float* __restrict__ obj2,
                    const float* __restrict__ boxes, const int* __restrict__ labels,
                    float* __restrict__ out)
{
    const float* clsp[3] = {cls0, cls1, cls2};
    const float* regp[3] = {reg0, reg1, reg2};
    const float* objp[3] = {obj0, obj1, obj2};

    int bid = blockIdx.x;
    int t = threadIdx.x;

    if (bid < SP_BLOCKS) {
        // ---- objectness softplus sum: 2 float4 per thread ----
        const float4* src;
        int base, lim;
        if (bid < SP0_BLOCKS) {
            src = (const float4*)obj0; base = bid * 512; lim = 25600;
        } else if (bid < SP0_BLOCKS + SP1_BLOCKS) {
            src = (const float4*)obj1; base = (bid - SP0_BLOCKS) * 512; lim = 6400;
        } else {
            src = (const float4*)obj2; base = (bid - SP0_BLOCKS - SP1_BLOCKS) * 512; lim = 1600;
        }
        int i0 = base + t, i1 = base + 256 + t;
        float acc = 0.0f;
        if (i0 < lim) {
            float4 v = src[i0];
            acc += softplus_f(v.x) + softplus_f(v.y) + softplus_f(v.z) + softplus_f(v.w);
        }
        if (i1 < lim) {
            float4 v = src[i1];
            acc += softplus_f(v.x) + softplus_f(v.y) + softplus_f(v.z) + softplus_f(v.w);
        }
        float tot = blk_reduce(acc);
        if (t == 0) __stcg(&g_blk_sp[bid], tot);
    } else {
        // ---- per (scale, batch): 4 threads per box ----
        int idx = bid - SP_BLOCKS;
        int s = idx >> 4;          // 0..2
        int b = idx & 15;          // 0..15
        int Wd = 80 >> s;          // 80, 40, 20
        int HW = Wd * Wd;

        int box  = t >> 2;         // 0..63
        int part = t & 3;          // 0..3

        __shared__ int spk[NBOX];  // packed (cell<<5)|label

        // box coords + cell (all 4 parts compute identically; broadcast loads)
        const float4 bx = ((const float4*)boxes)[b * NBOX + box];
        int gx = (int)(bx.x * (float)Wd);
        int gy = (int)(bx.y * (float)Wd);
        gx = max(0, min(gx, Wd - 1));
        gy = max(0, min(gy, Wd - 1));
        int cell = gy * Wd + gx;
        int lab  = labels[b * NBOX + box];
        int mypk = (cell << 5) | lab;
        if (part == 0) spk[box] = mypk;

        // ---- speculative gathers (issued before the barrier; scattered) ----
        // classes: part p covers [8p, 8p+8) (part 3: 6 real + 2 padded)
        int cbase = part * 8;
        const float* cp = clsp[s] + (size_t)b * NCLS * HW + cell;
        float v[8];
        #pragma unroll
        for (int i = 0; i < 8; i++) {
            int c = cbase + i;
            int cc = min(c, NCLS - 1);
            float val = __ldg(&cp[(size_t)cc * HW]);
            v[i] = (c < NCLS) ? val : -1e30f;
        }
        // reg: part p loads coordinate p
        float regv = __ldg(&regp[s][(size_t)b * 4 * HW + (size_t)part * HW + cell]);
        // obj: part 3 loads it
        float objv = (part == 3) ? __ldg(&objp[s][(size_t)b * HW + cell]) : 0.0f;
        __syncthreads();

        // ---- collision resolution: fully unrolled, branchless ----
        int mlpk = mypk;
        int lose = 0;
        #pragma unroll
        for (int j = 0; j < NBOX; j++) {
            int pj = spk[j];
            bool eq = (((pj ^ mypk) & ~31) == 0);   // same cell
            mlpk = (eq && pj < mlpk) ? pj : mlpk;    // min label among same-cell boxes
            lose |= (eq && j > box) ? 1 : 0;         // a later box overwrites this cell
        }
        int ml = mlpk & 31;
        bool winner = (lose == 0);

        // ---- group-of-4 combine (contiguous lanes, same warp) ----
        float m = v[0];
        #pragma unroll
        for (int i = 1; i < 8; i++) m = fmaxf(m, v[i]);
        m = fmaxf(m, __shfl_xor_sync(0xffffffffu, m, 1));
        m = fmaxf(m, __shfl_xor_sync(0xffffffffu, m, 2));

        float ssum = 0.0f, tgt = 0.0f;
        #pragma unroll
        for (int i = 0; i < 8; i++) {
            int c = cbase + i;
            ssum += __expf(v[i] - m);                // padded entries -> exp(-huge)=0
            tgt = (c == ml) ? v[i] : tgt;
        }
        float bc = (part == 0) ? bx.x : (part == 1) ? bx.y : (part == 2) ? bx.z : bx.w;
        float d = fabsf(regv - bc);
        float sl = (d < 1.0f) ? 0.5f * d * d : d - 0.5f;

        ssum += __shfl_xor_sync(0xffffffffu, ssum, 1);
        ssum += __shfl_xor_sync(0xffffffffu, ssum, 2);
        tgt  += __shfl_xor_sync(0xffffffffu, tgt, 1);
        tgt  += __shfl_xor_sync(0xffffffffu, tgt, 2);
        sl   += __shfl_xor_sync(0xffffffffu, sl, 1);
        sl   += __shfl_xor_sync(0xffffffffu, sl, 2);

        float cls_l = 0.0f, reg_l = 0.0f, objp_l = 0.0f, np_l = 0.0f;
        if (winner) {
            if (part == 0) {
                np_l  = 1.0f;
                cls_l = m + __logf(ssum) - tgt;
                reg_l = fminf(sl * 0.25f, 10.0f);
            }
            if (part == 3) objp_l = objv;
        }
        __shared__ float res[4];
        blk_reduce4(cls_l, reg_l, objp_l, np_l, res);
        if (t == 0) {
            float4 o4 = make_float4(res[0], res[1], res[2], res[3]);
            __stcg(&g_blk_as[idx], o4);
        }
    }

    // ---- last arriving block: deterministic final reduce ----
    __shared__ bool amLast;
    if (t == 0) {
        __threadfence();   // order this block's partial store before the ticket
        unsigned vv = atomicAdd(&g_done, 1u);
        amLast = (vv == (unsigned)(gridDim.x - 1));
        if (amLast) __threadfence();   // acquire: see all other blocks' partials
    }
    __syncthreads();
    if (!amLast) return;

    // softplus partials: one load per thread, fused 3-way reduce
    float l0 = 0.f, l1 = 0.f, l2 = 0.f;
    if (t < SP_BLOCKS) {
        float pv = __ldcg(&g_blk_sp[t]);
        if (t < SP0_BLOCKS) l0 = pv;
        else if (t < SP0_BLOCKS + SP1_BLOCKS) l1 = pv;
        else l2 = pv;
    }
    __shared__ float spr[4];
    blk_reduce4(l0, l1, l2, 0.0f, spr);

    // assignment partials: thread-parallel, 3 masked passes (one per scale)
    float4 a4 = make_float4(0.f, 0.f, 0.f, 0.f);
    if (t < AS_BLOCKS) a4 = __ldcg(&g_blk_as[t]);
    int myscale = t >> 4;
    __shared__ float asr[3][4];
    #pragma unroll
    for (int s = 0; s < 3; s++) {
        bool on = (t < AS_BLOCKS) && (myscale == s);
        __shared__ float tmp[4];
        blk_reduce4(on ? a4.x : 0.f, on ? a4.y : 0.f, on ? a4.z : 0.f, on ? a4.w : 0.f, tmp);
        if (t == 0) { asr[s][0] = tmp[0]; asr[s][1] = tmp[1]; asr[s][2] = tmp[2]; asr[s][3] = tmp[3]; }
    }

    if (t == 0) {
        float cls_tot = 0.0f, reg_tot = 0.0f, obj_tot = 0.0f;
        #pragma unroll
        for (int s = 0; s < 3; s++) {
            float npos = fmaxf(asr[s][3], 1.0f);
            int Wd = 80 >> s;
            float Ms = (float)(NBATCH * Wd * Wd);
            cls_tot += asr[s][0] / npos;               // CLS_W = 1
            reg_tot += asr[s][1] / npos * 5.0f;        // REG_W = 5
            obj_tot += (spr[s] - asr[s][2]) / Ms;      // OBJ_W = 1
        }
        cls_tot *= (1.0f / 3.0f);
        reg_tot *= (1.0f / 3.0f);
        obj_tot *= (1.0f / 3.0f);
        out[0] = cls_tot + reg_tot + obj_tot;
        out[1] = cls_tot;
        out[2] = reg_tot;
        out[3] = obj_tot;
        g_done = 0;   // reset for next graph replay
    }
}

extern "C" void kernel_launch(void* const* d_in, const int* in_sizes, int n_in,
                              void* d_out, int out_size)
{
    const float *cls[3], *reg[3], *obj[3];
    if (in_sizes[1] == 409600) {   // dict order: cls0,reg0,obj0,cls1,...
        cls[0] = (const float*)d_in[0]; reg[0] = (const float*)d_in[1]; obj[0] = (const float*)d_in[2];
        cls[1] = (const float*)d_in[3]; reg[1] = (const float*)d_in[4]; obj[1] = (const float*)d_in[5];
        cls[2] = (const float*)d_in[6]; reg[2] = (const float*)d_in[7]; obj[2] = (const float*)d_in[8];
    } else {                        // signature order: cls0,cls1,cls2,reg0,...
        cls[0] = (const float*)d_in[0]; cls[1] = (const float*)d_in[1]; cls[2] = (const float*)d_in[2];
        reg[0] = (const float*)d_in[3]; reg[1] = (const float*)d_in[4]; reg[2] = (const float*)d_in[5];
        obj[0] = (const float*)d_in[6]; obj[1] = (const float*)d_in[7]; obj[2] = (const float*)d_in[8];
    }
    const float* boxes  = (const float*)d_in[9];
    const int*   labels = (const int*)d_in[10];
    float* out = (float*)d_out;

    detloss_kernel<<<TOTAL_BLOCKS, TPB>>>(
        cls[0], cls[1], cls[2],
        reg[0], reg[1], reg[2],
        obj[0], obj[1], obj[2],
        boxes, labels, out);
}